// round 1
// baseline (speedup 1.0000x reference)
#include <cuda_runtime.h>

#define NN   4096
#define FIN  68
#define HID  64
#define GG   128
#define FPD  167
#define MAXD 256   // max neighbors per row; E[deg]~42, P(deg>128) ~ 1e-40. Safe.

// ---------------- device scratch (no allocations allowed) ----------------
__device__ int   g_col[NN * MAXD];
__device__ int   g_deg[NN];
__device__ float g_Wh[NN * HID];
__device__ float g_sv[NN];
__device__ float g_dv[NN];
__device__ float g_hA[NN * HID];
__device__ float g_hB[NN * HID];
__device__ float g_Weff[2 * HID * HID];
__device__ float g_pool[GG * HID];
__device__ float g_cnt[GG];

// ---------------- 1) CSR build: warp per row, float4 loads ----------------
__global__ void build_csr_kernel(const float* __restrict__ adj) {
    int warp = (blockIdx.x * blockDim.x + threadIdx.x) >> 5;
    int lane = threadIdx.x & 31;
    if (warp >= NN) return;
    const float4* row = (const float4*)(adj + (size_t)warp * NN);
    int* cols = g_col + (size_t)warp * MAXD;
    int count = 0;
    for (int base = 0; base < NN / 4; base += 32) {
        float4 v = row[base + lane];
        int b0 = v.x > 0.f, b1 = v.y > 0.f, b2 = v.z > 0.f, b3 = v.w > 0.f;
        int cnt = b0 + b1 + b2 + b3;
        // inclusive warp scan
        int sc = cnt;
        #pragma unroll
        for (int o = 1; o < 32; o <<= 1) {
            int t = __shfl_up_sync(0xffffffffu, sc, o);
            if (lane >= o) sc += t;
        }
        int total = __shfl_sync(0xffffffffu, sc, 31);
        int off = count + sc - cnt;       // exclusive prefix
        int idx0 = (base + lane) * 4;
        if (b0 && off < MAXD) cols[off] = idx0;     off += b0;
        if (b1 && off < MAXD) cols[off] = idx0 + 1; off += b1;
        if (b2 && off < MAXD) cols[off] = idx0 + 2; off += b2;
        if (b3 && off < MAXD) cols[off] = idx0 + 3;
        count += total;
    }
    if (lane == 0) g_deg[warp] = min(count, MAXD);
}

// ------------- 2) collapse head-tiled weight matrices: W_eff -------------
__global__ void reduce_w_kernel(const float* __restrict__ W1,
                                const float* __restrict__ W2) {
    int i = blockIdx.x * blockDim.x + threadIdx.x;   // 0 .. 4095
    if (i >= HID * HID) return;
    int k = i / HID, c = i % HID;
    float s1 = 0.f, s2 = 0.f;
    #pragma unroll
    for (int t = 0; t < 4; t++) {
        s1 += W1[(k + HID * t) * HID + c];
        s2 += W2[(k + HID * t) * HID + c];
    }
    g_Weff[i]             = s1;
    g_Weff[HID * HID + i] = s2;
}

__global__ void zero_pool_kernel() {
    int i = blockIdx.x * blockDim.x + threadIdx.x;
    if (i < GG * HID) g_pool[i] = 0.f;
    if (i < GG)       g_cnt[i]  = 0.f;
}

// ------------- 3) Wh = h @ W, plus s = Wh.a_src, d = Wh.a_dst -------------
// block per node row, 64 threads (one per out channel)
// hsel: 0 -> use hparam (x input); 1 -> g_hA; 2 -> g_hB
// wsel: 0 -> use Wparam;           1 -> g_Weff; 2 -> g_Weff+4096
template <int K>
__global__ void wh_kernel(const float* __restrict__ hparam, int hsel,
                          const float* __restrict__ Wparam, int wsel,
                          const float* __restrict__ asrc,
                          const float* __restrict__ adst) {
    __shared__ float hrow[K];
    __shared__ float red[4];
    const float* h = (hsel == 0) ? hparam : (hsel == 1 ? g_hA : g_hB);
    const float* W = (wsel == 0) ? Wparam : (wsel == 1 ? g_Weff : g_Weff + HID * HID);
    int row = blockIdx.x;
    int c   = threadIdx.x;
    for (int k = c; k < K; k += HID) hrow[k] = h[(size_t)row * K + k];
    __syncthreads();
    float acc = 0.f;
    #pragma unroll
    for (int k = 0; k < K; k++) acc += hrow[k] * W[k * HID + c];
    g_Wh[row * HID + c] = acc;
    float ps = acc * asrc[c];
    float pd = acc * adst[c];
    #pragma unroll
    for (int o = 16; o > 0; o >>= 1) {
        ps += __shfl_down_sync(0xffffffffu, ps, o);
        pd += __shfl_down_sync(0xffffffffu, pd, o);
    }
    if ((c & 31) == 0) { red[c >> 5] = ps; red[2 + (c >> 5)] = pd; }
    __syncthreads();
    if (c == 0) { g_sv[row] = red[0] + red[1]; g_dv[row] = red[2] + red[3]; }
}

// ------------- 4) sparse softmax attention, warp per node, +ReLU ----------
__global__ void attn_kernel(int dstsel) {
    __shared__ float wbuf[8][MAXD];
    int warp = (blockIdx.x * blockDim.x + threadIdx.x) >> 5;
    int lane = threadIdx.x & 31;
    if (warp >= NN) return;
    float* wts = wbuf[(threadIdx.x >> 5)];
    float* out = (dstsel == 1) ? g_hA : g_hB;

    int deg = g_deg[warp];
    const int* cols = g_col + (size_t)warp * MAXD;
    float si = g_sv[warp];

    float m = -1e30f;
    for (int j = lane; j < deg; j += 32) {
        float e = si + g_dv[cols[j]];
        e = (e > 0.f) ? e : 0.2f * e;     // leaky_relu(0.2)
        wts[j] = e;
        m = fmaxf(m, e);
    }
    #pragma unroll
    for (int o = 16; o > 0; o >>= 1) m = fmaxf(m, __shfl_xor_sync(0xffffffffu, m, o));

    float ssum = 0.f;
    for (int j = lane; j < deg; j += 32) {
        float w = __expf(wts[j] - m);
        wts[j] = w;
        ssum += w;
    }
    #pragma unroll
    for (int o = 16; o > 0; o >>= 1) ssum += __shfl_xor_sync(0xffffffffu, ssum, o);
    float inv = 1.f / ssum;
    __syncwarp();

    float a0 = 0.f, a1 = 0.f;
    for (int j = 0; j < deg; j++) {
        float w = wts[j];
        const float* whr = g_Wh + (size_t)cols[j] * HID;
        a0 += w * whr[lane];
        a1 += w * whr[lane + 32];
    }
    out[(size_t)warp * HID + lane]      = fmaxf(a0 * inv, 0.f);
    out[(size_t)warp * HID + lane + 32] = fmaxf(a1 * inv, 0.f);
}

// ------------- 5) segment-sum pooling (atomics), reads g_hA ---------------
__global__ void pool_kernel(const int* __restrict__ batch) {
    int node = blockIdx.x;
    int c    = threadIdx.x;
    int b    = batch[node];
    atomicAdd(&g_pool[b * HID + c], g_hA[(size_t)node * HID + c]);
    if (c == 0) atomicAdd(&g_cnt[b], 1.f);
}

// ------------- 6) fingerprint branch + final FC, block per graph ----------
__global__ void final_kernel(const float* __restrict__ fp,
                             const float* __restrict__ fc1w,
                             const float* __restrict__ fc1b,
                             const float* __restrict__ fcw,
                             const float* __restrict__ fcb,
                             float* __restrict__ out) {
    __shared__ float red[2];
    int g = blockIdx.x;
    int c = threadIdx.x;   // 64
    float acc = fc1b[c];
    for (int k = 0; k < FPD; k++) acc += fp[g * FPD + k] * fc1w[k * HID + c];
    acc = fmaxf(acc, 0.f);                               // fp_embed[c]
    float gnn  = g_pool[g * HID + c] / fmaxf(g_cnt[g], 1.f);
    float part = gnn * fcw[c] + acc * fcw[HID + c];
    #pragma unroll
    for (int o = 16; o > 0; o >>= 1) part += __shfl_down_sync(0xffffffffu, part, o);
    if ((c & 31) == 0) red[c >> 5] = part;
    __syncthreads();
    if (c == 0) out[g] = fmaxf(red[0] + red[1] + fcb[0], 0.f);
}

// --------------------------------------------------------------------------
extern "C" void kernel_launch(void* const* d_in, const int* in_sizes, int n_in,
                              void* d_out, int out_size) {
    const float* x     = (const float*)d_in[0];
    const float* adj   = (const float*)d_in[1];
    const int*   batch = (const int*)  d_in[2];
    const float* fp    = (const float*)d_in[3];
    const float* W0    = (const float*)d_in[4];
    const float* as0   = (const float*)d_in[5];
    const float* ad0   = (const float*)d_in[6];
    const float* W1    = (const float*)d_in[7];
    const float* as1   = (const float*)d_in[8];
    const float* ad1   = (const float*)d_in[9];
    const float* W2    = (const float*)d_in[10];
    const float* as2   = (const float*)d_in[11];
    const float* ad2   = (const float*)d_in[12];
    const float* fc1w  = (const float*)d_in[13];
    const float* fc1b  = (const float*)d_in[14];
    const float* fcw   = (const float*)d_in[15];
    const float* fcb   = (const float*)d_in[16];
    float* out = (float*)d_out;

    build_csr_kernel<<<NN / 8, 256>>>(adj);
    reduce_w_kernel<<<(HID * HID + 255) / 256, 256>>>(W1, W2);
    zero_pool_kernel<<<(GG * HID + 255) / 256, 256>>>();

    // layer 0
    wh_kernel<FIN><<<NN, HID>>>(x, 0, W0, 0, as0, ad0);
    attn_kernel<<<NN / 8, 256>>>(1);                    // -> g_hA
    // layer 1
    wh_kernel<HID><<<NN, HID>>>(nullptr, 1, nullptr, 1, as1, ad1);
    attn_kernel<<<NN / 8, 256>>>(2);                    // -> g_hB
    // layer 2
    wh_kernel<HID><<<NN, HID>>>(nullptr, 2, nullptr, 2, as2, ad2);
    attn_kernel<<<NN / 8, 256>>>(1);                    // -> g_hA

    pool_kernel<<<NN, HID>>>(batch);
    final_kernel<<<GG, HID>>>(fp, fc1w, fc1b, fcw, fcb, out);
}

// round 2
// speedup vs baseline: 1.2106x; 1.2106x over previous
#include <cuda_runtime.h>

#define NN   4096
#define FIN  68
#define HID  64
#define GG   128
#define FPD  167
#define MAXD 256   // per-row cap; E[deg]~42, P(>256) ~ 0
#define CMAX 64    // per-512-col-chunk cap; Binomial(512,0.01) mean ~5

// ---------------- device scratch (no allocations allowed) ----------------
__device__ int   g_col[NN * MAXD];
__device__ int   g_deg[NN];
__device__ float g_Wh[NN * HID];
__device__ float g_sv[NN];
__device__ float g_dv[NN];
__device__ float g_hA[NN * HID];
__device__ float g_hB[NN * HID];
__device__ float g_Weff[2 * HID * HID];
__device__ float g_pool[GG * HID];
__device__ float g_cnt[GG];

// ------- 1) CSR build: block per row, 8 warps x 4 prefetched float4 -------
__global__ void build_csr_kernel(const float* __restrict__ adj) {
    __shared__ int cbuf[8][CMAX];
    __shared__ int ccnt[8];
    __shared__ int coff[8];
    int row  = blockIdx.x;
    int w    = threadIdx.x >> 5;
    int lane = threadIdx.x & 31;
    const float4* rp = (const float4*)(adj + (size_t)row * NN);

    float4 v[4];
    #pragma unroll
    for (int it = 0; it < 4; it++) v[it] = rp[(w << 7) + (it << 5) + lane];

    int count = 0;
    #pragma unroll
    for (int it = 0; it < 4; it++) {
        int b0 = v[it].x > 0.f, b1 = v[it].y > 0.f;
        int b2 = v[it].z > 0.f, b3 = v[it].w > 0.f;
        int cnt = b0 + b1 + b2 + b3;
        int sc = cnt;
        #pragma unroll
        for (int o = 1; o < 32; o <<= 1) {
            int t = __shfl_up_sync(0xffffffffu, sc, o);
            if (lane >= o) sc += t;
        }
        int total = __shfl_sync(0xffffffffu, sc, 31);
        int off = count + sc - cnt;
        int idx0 = ((w << 7) + (it << 5) + lane) << 2;
        if (b0 && off < CMAX) cbuf[w][off] = idx0;     off += b0;
        if (b1 && off < CMAX) cbuf[w][off] = idx0 + 1; off += b1;
        if (b2 && off < CMAX) cbuf[w][off] = idx0 + 2; off += b2;
        if (b3 && off < CMAX) cbuf[w][off] = idx0 + 3;
        count += total;
    }
    if (lane == 0) ccnt[w] = min(count, CMAX);
    __syncthreads();
    if (threadIdx.x == 0) {
        int s = 0;
        #pragma unroll
        for (int i = 0; i < 8; i++) { coff[i] = s; s += ccnt[i]; }
        g_deg[row] = min(s, MAXD);
    }
    __syncthreads();
    int off = coff[w], n = ccnt[w];
    for (int j = lane; j < n; j += 32) {
        int p = off + j;
        if (p < MAXD) g_col[(size_t)row * MAXD + p] = cbuf[w][j];
    }
}

// ---- 2) prep: collapse head-tiled W1/W2 into W_eff + zero pool bufs ----
__global__ void prep_kernel(const float* __restrict__ W1,
                            const float* __restrict__ W2) {
    int i = blockIdx.x * blockDim.x + threadIdx.x;   // 0 .. 8191
    if (i < HID * HID) {
        int k = i / HID, c = i % HID;
        float s1 = 0.f, s2 = 0.f;
        #pragma unroll
        for (int t = 0; t < 4; t++) {
            s1 += W1[(k + HID * t) * HID + c];
            s2 += W2[(k + HID * t) * HID + c];
        }
        g_Weff[i]             = s1;
        g_Weff[HID * HID + i] = s2;
    }
    if (i < GG * HID) g_pool[i] = 0.f;
    if (i < GG)       g_cnt[i]  = 0.f;
}

// ---- 3) Wh = h @ W fused with s = Wh.a_src, d = Wh.a_dst -----------------
// 256 threads = 4 rows x 64 cols, grid = NN/4. W read through L1 (17KB hot).
template <int K>
__global__ void wh_kernel(const float* __restrict__ hparam, int hsel,
                          const float* __restrict__ Wparam, int wsel,
                          const float* __restrict__ asrc,
                          const float* __restrict__ adst) {
    __shared__ float hs[4][K];
    __shared__ float red[4][2][2];   // [row][s/d][warp-half]
    const float* h = (hsel == 0) ? hparam : (hsel == 1 ? g_hA : g_hB);
    const float* W = (wsel == 0) ? Wparam : (wsel == 1 ? g_Weff : g_Weff + HID * HID);
    int c = threadIdx.x & 63;
    int r = threadIdx.x >> 6;
    int row0 = blockIdx.x * 4;
    // tile is contiguous: rows row0..row0+3
    for (int idx = threadIdx.x; idx < 4 * K; idx += 256)
        hs[idx / K][idx % K] = h[(size_t)row0 * K + idx];
    __syncthreads();
    float acc = 0.f;
    #pragma unroll
    for (int k = 0; k < K; k++) acc += hs[r][k] * __ldg(&W[k * HID + c]);
    g_Wh[(size_t)(row0 + r) * HID + c] = acc;
    float ps = acc * asrc[c];
    float pd = acc * adst[c];
    #pragma unroll
    for (int o = 16; o > 0; o >>= 1) {
        ps += __shfl_down_sync(0xffffffffu, ps, o);
        pd += __shfl_down_sync(0xffffffffu, pd, o);
    }
    if ((threadIdx.x & 31) == 0) {
        int half = (c >> 5);
        red[r][0][half] = ps;
        red[r][1][half] = pd;
    }
    __syncthreads();
    if (c == 0) {
        g_sv[row0 + r] = red[r][0][0] + red[r][0][1];
        g_dv[row0 + r] = red[r][1][0] + red[r][1][1];
    }
}

// ---- 4) sparse softmax attention, warp/node, float2 gather, +ReLU --------
// dstsel: 1 -> g_hA, 2 -> g_hB, 3 -> pool atomics (final layer, no h write)
__global__ void attn_kernel(int dstsel, const int* __restrict__ batch) {
    __shared__ float wbuf[8][MAXD];
    int warp = (blockIdx.x * blockDim.x + threadIdx.x) >> 5;
    int lane = threadIdx.x & 31;
    if (warp >= NN) return;
    float* wts = wbuf[threadIdx.x >> 5];

    int deg = g_deg[warp];
    const int* cols = g_col + (size_t)warp * MAXD;
    float si = g_sv[warp];

    float m = -1e30f;
    for (int j = lane; j < deg; j += 32) {
        float e = si + g_dv[cols[j]];
        e = (e > 0.f) ? e : 0.2f * e;     // leaky_relu(0.2)
        wts[j] = e;
        m = fmaxf(m, e);
    }
    #pragma unroll
    for (int o = 16; o > 0; o >>= 1) m = fmaxf(m, __shfl_xor_sync(0xffffffffu, m, o));

    float ssum = 0.f;
    for (int j = lane; j < deg; j += 32) {
        float w = __expf(wts[j] - m);
        wts[j] = w;
        ssum += w;
    }
    #pragma unroll
    for (int o = 16; o > 0; o >>= 1) ssum += __shfl_xor_sync(0xffffffffu, ssum, o);
    float inv = 1.f / ssum;
    __syncwarp();

    float a0 = 0.f, a1 = 0.f;
    for (int j = 0; j < deg; j++) {
        float w = wts[j];
        float2 v = ((const float2*)(g_Wh + (size_t)cols[j] * HID))[lane];
        a0 += w * v.x;
        a1 += w * v.y;
    }
    a0 = fmaxf(a0 * inv, 0.f);
    a1 = fmaxf(a1 * inv, 0.f);
    if (dstsel == 3) {
        int b = batch[warp];
        atomicAdd(&g_pool[b * HID + 2 * lane],     a0);
        atomicAdd(&g_pool[b * HID + 2 * lane + 1], a1);
        if (lane == 0) atomicAdd(&g_cnt[b], 1.f);
    } else {
        float* out = (dstsel == 1) ? g_hA : g_hB;
        ((float2*)(out + (size_t)warp * HID))[lane] = make_float2(a0, a1);
    }
}

// ---- 5) fingerprint branch + final FC, block per graph -------------------
__global__ void final_kernel(const float* __restrict__ fp,
                             const float* __restrict__ fc1w,
                             const float* __restrict__ fc1b,
                             const float* __restrict__ fcw,
                             const float* __restrict__ fcb,
                             float* __restrict__ out) {
    __shared__ float red[2];
    int g = blockIdx.x;
    int c = threadIdx.x;   // 64
    float acc = fc1b[c];
    for (int k = 0; k < FPD; k++) acc += fp[g * FPD + k] * __ldg(&fc1w[k * HID + c]);
    acc = fmaxf(acc, 0.f);                               // fp_embed[c]
    float gnn  = g_pool[g * HID + c] / fmaxf(g_cnt[g], 1.f);
    float part = gnn * fcw[c] + acc * fcw[HID + c];
    #pragma unroll
    for (int o = 16; o > 0; o >>= 1) part += __shfl_down_sync(0xffffffffu, part, o);
    if ((c & 31) == 0) red[c >> 5] = part;
    __syncthreads();
    if (c == 0) out[g] = fmaxf(red[0] + red[1] + fcb[0], 0.f);
}

// --------------------------------------------------------------------------
extern "C" void kernel_launch(void* const* d_in, const int* in_sizes, int n_in,
                              void* d_out, int out_size) {
    const float* x     = (const float*)d_in[0];
    const float* adj   = (const float*)d_in[1];
    const int*   batch = (const int*)  d_in[2];
    const float* fp    = (const float*)d_in[3];
    const float* W0    = (const float*)d_in[4];
    const float* as0   = (const float*)d_in[5];
    const float* ad0   = (const float*)d_in[6];
    const float* W1    = (const float*)d_in[7];
    const float* as1   = (const float*)d_in[8];
    const float* ad1   = (const float*)d_in[9];
    const float* W2    = (const float*)d_in[10];
    const float* as2   = (const float*)d_in[11];
    const float* ad2   = (const float*)d_in[12];
    const float* fc1w  = (const float*)d_in[13];
    const float* fc1b  = (const float*)d_in[14];
    const float* fcw   = (const float*)d_in[15];
    const float* fcb   = (const float*)d_in[16];
    float* out = (float*)d_out;

    build_csr_kernel<<<NN, 256>>>(adj);
    prep_kernel<<<(GG * HID + 255) / 256, 256>>>(W1, W2);

    // layer 0
    wh_kernel<FIN><<<NN / 4, 256>>>(x, 0, W0, 0, as0, ad0);
    attn_kernel<<<NN / 8, 256>>>(1, batch);             // -> g_hA
    // layer 1
    wh_kernel<HID><<<NN / 4, 256>>>(nullptr, 1, nullptr, 1, as1, ad1);
    attn_kernel<<<NN / 8, 256>>>(2, batch);             // -> g_hB
    // layer 2
    wh_kernel<HID><<<NN / 4, 256>>>(nullptr, 2, nullptr, 2, as2, ad2);
    attn_kernel<<<NN / 8, 256>>>(3, batch);             // -> pool atomics

    final_kernel<<<GG, HID>>>(fp, fc1w, fc1b, fcw, fcb, out);
}